// round 16
// baseline (speedup 1.0000x reference)
#include <cuda_runtime.h>
#include <cuda_bf16.h>
#include <cstdint>
#include <climits>

#define DIM    768
#define KC     2048
#define NROWS  16384
#define BM     128               // rows per unit
#define BN     128               // codes per unit
#define BK     64                // bf16 elems per chunk = 128 B/row
#define CHUNKS (DIM / BK)        // 12
#define NUNITS ((NROWS / BM) * (KC / BN))  // 2048
#define NCTA   296               // 2 CTAs per SM exactly
#define STAGE  32768             // A 16KB + B 16KB
#define QSCALE 131072.0f
#define QTHR_Q 85                // refine window in quanta (~6.5e-4)
#define NSLOT  64

__device__ float g_enorm[KC];
__device__ float g_zsum[NROWS];
__device__ float g_loss;
__device__ int   g_cnt;
__device__ unsigned g_ccnt[NROWS];
__device__ unsigned g_cand[(size_t)NROWS * NSLOT];   // packed (q+32768)<<16 | code
__device__ __nv_bfloat16 g_zhi[(size_t)NROWS * DIM];
__device__ __nv_bfloat16 g_ehi[(size_t)KC * DIM];

static __device__ __forceinline__ uint32_t smem_u32(const void* p) {
    uint32_t a;
    asm("{ .reg .u64 t; cvta.to.shared.u64 t, %1; cvt.u32.u64 %0, t; }" : "=r"(a) : "l"(p));
    return a;
}
#define CP_ASYNC16(dst, src) \
    asm volatile("cp.async.cg.shared.global [%0], [%1], 16;" :: "r"(dst), "l"(src))
#define CP_COMMIT() asm volatile("cp.async.commit_group;" ::: "memory")
#define LDMX4(r, addr) \
    asm volatile("ldmatrix.sync.aligned.m8n8.x4.shared.b16 {%0,%1,%2,%3}, [%4];" \
        : "=r"((r)[0]), "=r"((r)[1]), "=r"((r)[2]), "=r"((r)[3]) : "r"(addr))
#define MMA16816(d, a, b0_, b1_) \
    asm volatile("mma.sync.aligned.m16n8k16.row.col.f32.bf16.bf16.f32 " \
        "{%0,%1,%2,%3}, {%4,%5,%6,%7}, {%8,%9}, {%0,%1,%2,%3};" \
        : "+f"((d)[0]), "+f"((d)[1]), "+f"((d)[2]), "+f"((d)[3]) \
        : "r"((a)[0]), "r"((a)[1]), "r"((a)[2]), "r"((a)[3]), "r"(b0_), "r"(b1_))

// -------- merged prep: z + emb convert + norms + init (warp/row) --------
__global__ void prep_kernel(const float* __restrict__ z, const float* __restrict__ emb,
                            __nv_bfloat16* __restrict__ zd, __nv_bfloat16* __restrict__ ed) {
    int w    = (blockIdx.x * blockDim.x + threadIdx.x) >> 5;
    int lane = threadIdx.x & 31;
    if (w >= NROWS + KC) return;
    const bool isZ = (w < NROWS);
    const int row  = isZ ? w : (w - NROWS);
    const float2* s2 = (const float2*)((isZ ? z : emb) + (size_t)row * DIM);
    __nv_bfloat162* d2 = (__nv_bfloat162*)((isZ ? zd : ed) + (size_t)row * DIM);
    float acc = 0.f;
#pragma unroll
    for (int j = 0; j < DIM / 64; j++) {
        float2 v = s2[lane + j * 32];
        acc = fmaf(v.x, v.x, fmaf(v.y, v.y, acc));
        d2[lane + j * 32] = __halves2bfloat162(__float2bfloat16_rn(v.x),
                                               __float2bfloat16_rn(v.y));
    }
#pragma unroll
    for (int o = 16; o > 0; o >>= 1) acc += __shfl_down_sync(0xffffffffu, acc, o);
    if (lane == 0) {
        if (isZ) { g_zsum[row] = acc; g_ccnt[row] = 0u; }
        else     { g_enorm[row] = acc; }
        if (w == 0) { g_loss = 0.f; g_cnt = 0; }
    }
}

// -------- pass 1: persistent bf16 HMMA GEMM -> direct candidate emission --------
// 296 persistent CTAs x 128 thr (2/SM). Unit = 128 rows x 128 codes,
// 12 K-chunk iterations; pipeline runs seamlessly across unit boundaries.
// Epilogue: per (row,unit) emit codes with s <= smin_unit + 88/QSCALE.
__global__ __launch_bounds__(128, 2)
void vq_pass1_kernel() {
    extern __shared__ char smem_raw[];
    const uint32_t sb = (smem_u32(smem_raw) + 127u) & ~127u;
    const int tid  = threadIdx.x;
    const int lane = tid & 31;
    const int w    = tid >> 5;
    const int wr   = w >> 1;    // 0..1  rows 64 each
    const int wc   = w & 1;     // 0..1  cols 64 each

    // ---- cp.async addressing: 16 x 16B per thread per stage ----
    const int gr  = tid >> 3;          // base row 0..15
    const int gg  = tid & 7;           // granule 0..7
    const uint32_t swx = (uint32_t)((gg ^ (gr & 7)) << 4);
    const uint32_t da  = (uint32_t)(gr * 128) + swx;            // A dst base
    const uint32_t db  = 16384u + (uint32_t)(gr * 128) + swx;   // B dst base
    const size_t aoff = (size_t)gr * DIM + gg * 8;

    // ---- ldmatrix lane addressing ----
    const int arow = lane & 15;
    const int agr  = lane >> 4;
    const int brow = (lane & 7) + ((lane >> 4) & 1) * 8;
    const int bgr  = (lane >> 3) & 1;
    uint32_t a_rt[4]; int a_sw[4];
#pragma unroll
    for (int mt = 0; mt < 4; mt++) {
        int r = wr * 64 + mt * 16 + arow;
        a_rt[mt] = r * 128; a_sw[mt] = r & 7;
    }
    uint32_t b_rt[4]; int b_sw[4];
#pragma unroll
    for (int nb = 0; nb < 4; nb++) {
        int r = wc * 64 + nb * 16 + brow;
        b_rt[nb] = r * 128; b_sw[nb] = r & 7;
    }

    float acc[4][8][4];
#pragma unroll
    for (int mt = 0; mt < 4; mt++)
#pragma unroll
        for (int nt = 0; nt < 8; nt++)
#pragma unroll
            for (int q = 0; q < 4; q++) acc[mt][nt][q] = 0.f;

    // prologue: issue (unit=blockIdx.x, chunk=0) into buf 0
    {
        const __nv_bfloat16* pa = g_zhi + (size_t)(blockIdx.x >> 4) * BM * DIM + aoff;
        const __nv_bfloat16* pb = g_ehi + (size_t)(blockIdx.x & 15) * BN * DIM + aoff;
#pragma unroll
        for (int k = 0; k < 8; k++)
            CP_ASYNC16(sb + da + (uint32_t)k * 2048u, pa + (size_t)k * 16 * DIM);
#pragma unroll
        for (int k = 0; k < 8; k++)
            CP_ASYNC16(sb + db + (uint32_t)k * 2048u, pb + (size_t)k * 16 * DIM);
        CP_COMMIT();
    }

    int cu = blockIdx.x, cc = 0;   // compute unit/chunk
    int pu = blockIdx.x, pc = 0;   // last-issued unit/chunk
    int it = 0;

    while (cu < NUNITS) {
        asm volatile("cp.async.wait_group 0;" ::: "memory");
        __syncthreads();

        if (++pc == CHUNKS) { pc = 0; pu += NCTA; }
        const bool donx = pu < NUNITS;
        const uint32_t nst = sb + (uint32_t)((it + 1) & 1) * STAGE;
        const __nv_bfloat16* npa = g_zhi + (size_t)(pu >> 4) * BM * DIM + aoff + pc * BK;
        const __nv_bfloat16* npb = g_ehi + (size_t)(pu & 15) * BN * DIM + aoff + pc * BK;

        const uint32_t Ab = sb + (uint32_t)(it & 1) * STAGE;
        const uint32_t Bb = Ab + 16384u;

        uint32_t ah[2][16];
#pragma unroll
        for (int mt = 0; mt < 4; mt++) {    // prefetch ks=0 A
            uint32_t ad = Ab + a_rt[mt] + (uint32_t)((agr ^ a_sw[mt]) << 4);
            LDMX4(&ah[0][mt * 4], ad);
        }

#pragma unroll
        for (int ks = 0; ks < 4; ks++) {
            const int g0 = ks * 2;
            const int cur = ks & 1, nxt = cur ^ 1;
            uint32_t bh[16];
#pragma unroll
            for (int nb = 0; nb < 4; nb++) {
                uint32_t bd = Bb + b_rt[nb] + (uint32_t)(((g0 + bgr) ^ b_sw[nb]) << 4);
                LDMX4(&bh[nb * 4], bd);
            }
            if (ks < 3) {
#pragma unroll
                for (int mt = 0; mt < 4; mt++) {
                    uint32_t ad = Ab + a_rt[mt] + (uint32_t)(((g0 + 2 + agr) ^ a_sw[mt]) << 4);
                    LDMX4(&ah[nxt][mt * 4], ad);
                }
            }
            if (donx) {
                if (ks < 2) {
#pragma unroll
                    for (int k = ks * 4; k < ks * 4 + 4; k++)
                        CP_ASYNC16(nst + da + (uint32_t)k * 2048u, npa + (size_t)k * 16 * DIM);
                } else {
#pragma unroll
                    for (int k = (ks - 2) * 4; k < (ks - 2) * 4 + 4; k++)
                        CP_ASYNC16(nst + db + (uint32_t)k * 2048u, npb + (size_t)k * 16 * DIM);
                }
            }
#pragma unroll
            for (int mt = 0; mt < 4; mt++)
#pragma unroll
                for (int nt = 0; nt < 8; nt++) {
                    const int bo_ = (nt >> 1) * 4 + (nt & 1) * 2;
                    MMA16816(acc[mt][nt], &ah[cur][mt * 4], bh[bo_], bh[bo_ + 1]);
                }
        }
        if (donx) CP_COMMIT();

        // ---- unit end: per-row unit-min, emit candidates within +88/QSCALE ----
        if (cc == CHUNKS - 1) {
            const int rowB = (cu >> 4) * BM;
            const int colB = (cu & 15) * BN;
#pragma unroll
            for (int sl = 0; sl < 8; sl++) {
                const int mt = sl >> 1, h = sl & 1;
                float smin = 3.4e38f;
#pragma unroll
                for (int nt = 0; nt < 8; nt++) {
                    int cb = colB + wc * 64 + nt * 8 + (lane & 3) * 2;
                    float s0 = __ldg(&g_enorm[cb])     - 2.0f * acc[mt][nt][h * 2];
                    float s1 = __ldg(&g_enorm[cb + 1]) - 2.0f * acc[mt][nt][h * 2 + 1];
                    smin = fminf(smin, fminf(s0, s1));
                }
                smin = fminf(smin, __shfl_xor_sync(0xffffffffu, smin, 1));
                smin = fminf(smin, __shfl_xor_sync(0xffffffffu, smin, 2));
                const float thr = smin + 88.0f / QSCALE;
                const int row0 = rowB + wr * 64 + mt * 16 + h * 8 + (lane >> 2);
#pragma unroll
                for (int nt = 0; nt < 8; nt++) {
                    int cb = colB + wc * 64 + nt * 8 + (lane & 3) * 2;
                    float s0 = __ldg(&g_enorm[cb])     - 2.0f * acc[mt][nt][h * 2];
                    float s1 = __ldg(&g_enorm[cb + 1]) - 2.0f * acc[mt][nt][h * 2 + 1];
                    if (s0 <= thr) {
                        int q = max(-32767, min(32767, __float2int_rn(s0 * QSCALE)));
                        unsigned slot = atomicAdd(&g_ccnt[row0], 1u);
                        if (slot < NSLOT)
                            g_cand[(size_t)row0 * NSLOT + slot] =
                                ((unsigned)(q + 32768) << 16) | (unsigned)cb;
                    }
                    if (s1 <= thr) {
                        int q = max(-32767, min(32767, __float2int_rn(s1 * QSCALE)));
                        unsigned slot = atomicAdd(&g_ccnt[row0], 1u);
                        if (slot < NSLOT)
                            g_cand[(size_t)row0 * NSLOT + slot] =
                                ((unsigned)(q + 32768) << 16) | (unsigned)(cb + 1);
                    }
                    acc[mt][nt][h * 2] = 0.f;
                    acc[mt][nt][h * 2 + 1] = 0.f;
                }
            }
        }
        if (++cc == CHUNKS) { cc = 0; cu += NCTA; }
        ++it;
    }
}

// -------- refine: candidate-list argmin + gather + loss + finalize (warp/row) --------
__global__ __launch_bounds__(256)
void refine_kernel(const float* __restrict__ z, const float* __restrict__ emb,
                   float* __restrict__ ids_out, float* __restrict__ zq,
                   float* __restrict__ loss_out) {
    __shared__ float redl[8];
    const int w    = threadIdx.x >> 5;
    const int lane = threadIdx.x & 31;
    const int r    = blockIdx.x * 8 + w;

    const float zr = g_zsum[r];
    const unsigned total = g_ccnt[r];
    const int cnt = (int)min(total, (unsigned)NSLOT);

    // z row in registers (exact fp32)
    float zreg[24];
    const float* zrow = z + (size_t)r * DIM;
#pragma unroll
    for (int j = 0; j < 24; j++) zreg[j] = zrow[lane + j * 32];

    // load candidates (<=64), find qmin, filter to window
    const unsigned* cp = g_cand + (size_t)r * NSLOT;
    unsigned p0 = (lane < cnt)      ? cp[lane]      : 0xFFFFFFFFu;
    unsigned p1 = (lane + 32 < cnt) ? cp[lane + 32] : 0xFFFFFFFFu;
    unsigned mn = min(p0, p1);
#pragma unroll
    for (int o = 16; o > 0; o >>= 1) mn = min(mn, __shfl_xor_sync(0xffffffffu, mn, o));
    const int qthr = (int)(mn >> 16) - 32768 + QTHR_Q;

    int cand[2];
    int nc = 0;
    if (lane < cnt      && ((int)(p0 >> 16) - 32768) <= qthr) cand[nc++] = (int)(p0 & 0xFFFFu);
    if (lane + 32 < cnt && ((int)(p1 >> 16) - 32768) <= qthr) cand[nc++] = (int)(p1 & 0xFFFFu);

    // warp-cooperative exact rescore (reference rounding, first-index ties)
    float best = 3.4e38f;
    int   bi   = INT_MAX;
    if (total <= (unsigned)NSLOT) {
        unsigned m = __ballot_sync(0xffffffffu, nc > 0);
        while (m) {
            int l = __ffs(m) - 1;
            m &= m - 1;
            int kcnt = __shfl_sync(0xffffffffu, nc, l);
            for (int t = 0; t < kcnt; t++) {
                int cc = __shfl_sync(0xffffffffu, cand[t], l);
                const float* erow = emb + (size_t)cc * DIM;
                float d = 0.f;
#pragma unroll
                for (int j = 0; j < 24; j++) d = fmaf(zreg[j], erow[lane + j * 32], d);
#pragma unroll
                for (int o = 16; o > 0; o >>= 1) d += __shfl_xor_sync(0xffffffffu, d, o);
                float se = (zr + g_enorm[cc]) - 2.0f * d;   // fl(fl(zsum+enorm)-2*dot)
                if (se < best || (se == best && cc < bi)) { best = se; bi = cc; }
            }
        }
    } else {
        // overflow fallback (statistically unreachable): exact scan of all codes
        for (int cc = 0; cc < KC; cc++) {
            const float* erow = emb + (size_t)cc * DIM;
            float d = 0.f;
#pragma unroll
            for (int j = 0; j < 24; j++) d = fmaf(zreg[j], erow[lane + j * 32], d);
#pragma unroll
            for (int o = 16; o > 0; o >>= 1) d += __shfl_xor_sync(0xffffffffu, d, o);
            float se = (zr + g_enorm[cc]) - 2.0f * d;
            if (se < best || (se == best && cc < bi)) { best = se; bi = cc; }
        }
    }

    // gather z_q + commitment-loss partial
    const float* erow = emb + (size_t)bi * DIM;
    float* qrow = zq + (size_t)r * DIM;
    float lacc = 0.f;
#pragma unroll
    for (int j = 0; j < 24; j++) {
        float q = erow[lane + j * 32];
        qrow[lane + j * 32] = q;
        float dd = zreg[j] - q;
        lacc = fmaf(dd, dd, lacc);
    }
#pragma unroll
    for (int o = 16; o > 0; o >>= 1) lacc += __shfl_down_sync(0xffffffffu, lacc, o);
    if (lane == 0) {
        ids_out[r] = (float)bi;
        redl[w] = lacc;
    }
    __syncthreads();
    if (threadIdx.x == 0) {
        float t = 0.f;
#pragma unroll
        for (int i = 0; i < 8; i++) t += redl[i];
        atomicAdd(&g_loss, t);
        __threadfence();
        int old = atomicAdd(&g_cnt, 1);
        if (old == gridDim.x - 1) {
            float tot = atomicAdd(&g_loss, 0.f);
            *loss_out = 0.25f * (tot / (float)((long long)NROWS * DIM));
        }
    }
}

// ---------------- launch ----------------
extern "C" void kernel_launch(void* const* d_in, const int* in_sizes, int n_in,
                              void* d_out, int out_size) {
    (void)in_sizes; (void)n_in; (void)out_size;
    const float* z   = (const float*)d_in[0];
    const float* emb = (const float*)d_in[1];
    float* out   = (float*)d_out;
    float* zq    = out;                              // [NROWS*DIM]
    float* idsf  = out + (size_t)NROWS * DIM;        // [NROWS]
    float* lossp = idsf + NROWS;                     // [1]

    __nv_bfloat16 *zhi_p, *ehi_p;
    cudaGetSymbolAddress((void**)&zhi_p, g_zhi);
    cudaGetSymbolAddress((void**)&ehi_p, g_ehi);

    const int VQ_SMEM = 2 * STAGE + 128;            // 65664
    cudaFuncSetAttribute(vq_pass1_kernel, cudaFuncAttributeMaxDynamicSharedMemorySize, VQ_SMEM);

    prep_kernel<<<(NROWS + KC) / 8, 256>>>(z, emb, zhi_p, ehi_p);
    vq_pass1_kernel<<<NCTA, 128, VQ_SMEM>>>();
    refine_kernel<<<NROWS / 8, 256>>>(z, emb, idsf, zq, lossp);
}

// round 17
// speedup vs baseline: 1.5945x; 1.5945x over previous
#include <cuda_runtime.h>
#include <cuda_bf16.h>
#include <cstdint>
#include <climits>

#define DIM    768
#define KC     2048
#define NROWS  16384
#define BM     128               // rows per unit
#define BN     128               // codes per unit
#define BK     64                // bf16 elems per chunk = 128 B/row
#define CHUNKS (DIM / BK)        // 12
#define NUNITS ((NROWS / BM) * (KC / BN))  // 2048
#define NCTA   296               // 2 CTAs per SM exactly
#define STAGE  32768             // A 16KB + B 16KB
#define QSCALE 131072.0f
#define QTHR_Q 85                // refine window in quanta (~6.5e-4)

__device__ float g_enorm[KC];
__device__ float g_zsum[NROWS];
__device__ float g_loss;
__device__ int   g_cnt;
__device__ int   g_qmin[NROWS];
__device__ __nv_bfloat16 g_zhi[(size_t)NROWS * DIM];
__device__ __nv_bfloat16 g_ehi[(size_t)KC * DIM];
__device__ short g_si[(size_t)NROWS * KC];     // 64 MiB quantized scores

static __device__ __forceinline__ uint32_t smem_u32(const void* p) {
    uint32_t a;
    asm("{ .reg .u64 t; cvta.to.shared.u64 t, %1; cvt.u32.u64 %0, t; }" : "=r"(a) : "l"(p));
    return a;
}
#define CP_ASYNC16(dst, src) \
    asm volatile("cp.async.cg.shared.global [%0], [%1], 16;" :: "r"(dst), "l"(src))
#define CP_COMMIT() asm volatile("cp.async.commit_group;" ::: "memory")
#define LDMX4(r, addr) \
    asm volatile("ldmatrix.sync.aligned.m8n8.x4.shared.b16 {%0,%1,%2,%3}, [%4];" \
        : "=r"((r)[0]), "=r"((r)[1]), "=r"((r)[2]), "=r"((r)[3]) : "r"(addr))
#define MMA16816(d, a, b0_, b1_) \
    asm volatile("mma.sync.aligned.m16n8k16.row.col.f32.bf16.bf16.f32 " \
        "{%0,%1,%2,%3}, {%4,%5,%6,%7}, {%8,%9}, {%0,%1,%2,%3};" \
        : "+f"((d)[0]), "+f"((d)[1]), "+f"((d)[2]), "+f"((d)[3]) \
        : "r"((a)[0]), "r"((a)[1]), "r"((a)[2]), "r"((a)[3]), "r"(b0_), "r"(b1_))

// -------- merged prep: z + emb convert + norms + init (warp/row, float4 loads) --------
__global__ void prep_kernel(const float* __restrict__ z, const float* __restrict__ emb,
                            __nv_bfloat16* __restrict__ zd, __nv_bfloat16* __restrict__ ed) {
    int w    = (blockIdx.x * blockDim.x + threadIdx.x) >> 5;
    int lane = threadIdx.x & 31;
    if (w >= NROWS + KC) return;
    const bool isZ = (w < NROWS);
    const int row  = isZ ? w : (w - NROWS);
    const float4* s4 = (const float4*)((isZ ? z : emb) + (size_t)row * DIM);
    uint2* d4 = (uint2*)((isZ ? zd : ed) + (size_t)row * DIM);
    float acc = 0.f;
#pragma unroll
    for (int j = 0; j < DIM / 128; j++) {      // 6 iterations of 16B
        float4 v = s4[lane + j * 32];
        acc = fmaf(v.x, v.x, fmaf(v.y, v.y, acc));
        acc = fmaf(v.z, v.z, fmaf(v.w, v.w, acc));
        __nv_bfloat162 lo = __halves2bfloat162(__float2bfloat16_rn(v.x),
                                               __float2bfloat16_rn(v.y));
        __nv_bfloat162 hi = __halves2bfloat162(__float2bfloat16_rn(v.z),
                                               __float2bfloat16_rn(v.w));
        uint2 pk;
        pk.x = *(uint32_t*)&lo;
        pk.y = *(uint32_t*)&hi;
        d4[lane + j * 32] = pk;
    }
#pragma unroll
    for (int o = 16; o > 0; o >>= 1) acc += __shfl_down_sync(0xffffffffu, acc, o);
    if (lane == 0) {
        if (isZ) { g_zsum[row] = acc; g_qmin[row] = INT_MAX; }
        else     { g_enorm[row] = acc; }
        if (w == 0) { g_loss = 0.f; g_cnt = 0; }
    }
}

// -------- pass 1: persistent bf16 HMMA GEMM -> int16 scores + per-row qmin --------
// 296 persistent CTAs x 128 thr (exactly 2/SM). Unit = 128 rows x 128 codes,
// 12 K-chunk iterations; pipeline runs seamlessly across unit boundaries.
__global__ __launch_bounds__(128, 2)
void vq_pass1_kernel() {
    extern __shared__ char smem_raw[];
    const uint32_t sb = (smem_u32(smem_raw) + 127u) & ~127u;
    const int tid  = threadIdx.x;
    const int lane = tid & 31;
    const int w    = tid >> 5;
    const int wr   = w >> 1;    // 0..1  rows 64 each
    const int wc   = w & 1;     // 0..1  cols 64 each

    // ---- cp.async addressing: 16 x 16B per thread per stage ----
    const int gr  = tid >> 3;          // base row 0..15
    const int gg  = tid & 7;           // granule 0..7
    const uint32_t swx = (uint32_t)((gg ^ (gr & 7)) << 4);
    const uint32_t da  = (uint32_t)(gr * 128) + swx;            // A dst base
    const uint32_t db  = 16384u + (uint32_t)(gr * 128) + swx;   // B dst base
    const size_t aoff = (size_t)gr * DIM + gg * 8;

    // ---- ldmatrix lane addressing ----
    const int arow = lane & 15;
    const int agr  = lane >> 4;
    const int brow = (lane & 7) + ((lane >> 4) & 1) * 8;
    const int bgr  = (lane >> 3) & 1;
    uint32_t a_rt[4]; int a_sw[4];
#pragma unroll
    for (int mt = 0; mt < 4; mt++) {
        int r = wr * 64 + mt * 16 + arow;
        a_rt[mt] = r * 128; a_sw[mt] = r & 7;
    }
    uint32_t b_rt[4]; int b_sw[4];
#pragma unroll
    for (int nb = 0; nb < 4; nb++) {
        int r = wc * 64 + nb * 16 + brow;
        b_rt[nb] = r * 128; b_sw[nb] = r & 7;
    }

    float acc[4][8][4];
#pragma unroll
    for (int mt = 0; mt < 4; mt++)
#pragma unroll
        for (int nt = 0; nt < 8; nt++)
#pragma unroll
            for (int q = 0; q < 4; q++) acc[mt][nt][q] = 0.f;

    // prologue: issue (unit=blockIdx.x, chunk=0) into buf 0
    {
        const __nv_bfloat16* pa = g_zhi + (size_t)(blockIdx.x >> 4) * BM * DIM + aoff;
        const __nv_bfloat16* pb = g_ehi + (size_t)(blockIdx.x & 15) * BN * DIM + aoff;
#pragma unroll
        for (int k = 0; k < 8; k++)
            CP_ASYNC16(sb + da + (uint32_t)k * 2048u, pa + (size_t)k * 16 * DIM);
#pragma unroll
        for (int k = 0; k < 8; k++)
            CP_ASYNC16(sb + db + (uint32_t)k * 2048u, pb + (size_t)k * 16 * DIM);
        CP_COMMIT();
    }

    int cu = blockIdx.x, cc = 0;   // compute unit/chunk
    int pu = blockIdx.x, pc = 0;   // last-issued unit/chunk
    int it = 0;

    while (cu < NUNITS) {
        asm volatile("cp.async.wait_group 0;" ::: "memory");
        __syncthreads();

        if (++pc == CHUNKS) { pc = 0; pu += NCTA; }
        const bool donx = pu < NUNITS;
        const uint32_t nst = sb + (uint32_t)((it + 1) & 1) * STAGE;
        const __nv_bfloat16* npa = g_zhi + (size_t)(pu >> 4) * BM * DIM + aoff + pc * BK;
        const __nv_bfloat16* npb = g_ehi + (size_t)(pu & 15) * BN * DIM + aoff + pc * BK;

        const uint32_t Ab = sb + (uint32_t)(it & 1) * STAGE;
        const uint32_t Bb = Ab + 16384u;

        uint32_t ah[2][16];
#pragma unroll
        for (int mt = 0; mt < 4; mt++) {    // prefetch ks=0 A
            uint32_t ad = Ab + a_rt[mt] + (uint32_t)((agr ^ a_sw[mt]) << 4);
            LDMX4(&ah[0][mt * 4], ad);
        }

#pragma unroll
        for (int ks = 0; ks < 4; ks++) {
            const int g0 = ks * 2;
            const int cur = ks & 1, nxt = cur ^ 1;
            uint32_t bh[16];
#pragma unroll
            for (int nb = 0; nb < 4; nb++) {
                uint32_t bd = Bb + b_rt[nb] + (uint32_t)(((g0 + bgr) ^ b_sw[nb]) << 4);
                LDMX4(&bh[nb * 4], bd);
            }
            if (ks < 3) {
#pragma unroll
                for (int mt = 0; mt < 4; mt++) {
                    uint32_t ad = Ab + a_rt[mt] + (uint32_t)(((g0 + 2 + agr) ^ a_sw[mt]) << 4);
                    LDMX4(&ah[nxt][mt * 4], ad);
                }
            }
            if (donx) {
                if (ks < 2) {
#pragma unroll
                    for (int k = ks * 4; k < ks * 4 + 4; k++)
                        CP_ASYNC16(nst + da + (uint32_t)k * 2048u, npa + (size_t)k * 16 * DIM);
                } else {
#pragma unroll
                    for (int k = (ks - 2) * 4; k < (ks - 2) * 4 + 4; k++)
                        CP_ASYNC16(nst + db + (uint32_t)k * 2048u, npb + (size_t)k * 16 * DIM);
                }
            }
#pragma unroll
            for (int mt = 0; mt < 4; mt++)
#pragma unroll
                for (int nt = 0; nt < 8; nt++) {
                    const int bo_ = (nt >> 1) * 4 + (nt & 1) * 2;
                    MMA16816(acc[mt][nt], &ah[cur][mt * 4], bh[bo_], bh[bo_ + 1]);
                }
        }
        if (donx) CP_COMMIT();

        // ---- unit end: dequantize -> int16 store + per-row qmin ----
        if (cc == CHUNKS - 1) {
            const int rowB = (cu >> 4) * BM;
            const int colB = (cu & 15) * BN;
            int qmn[8];
#pragma unroll
            for (int sl = 0; sl < 8; sl++) qmn[sl] = 32767;
#pragma unroll
            for (int nt = 0; nt < 8; nt++) {
                int cb = colB + wc * 64 + nt * 8 + (lane & 3) * 2;
                float e0 = __ldg(&g_enorm[cb]);
                float e1 = __ldg(&g_enorm[cb + 1]);
#pragma unroll
                for (int mt = 0; mt < 4; mt++)
#pragma unroll
                    for (int h = 0; h < 2; h++) {
                        const int sl = mt * 2 + h;
                        float d0 = acc[mt][nt][h * 2], d1 = acc[mt][nt][h * 2 + 1];
                        int q0 = __float2int_rn(fminf(fmaxf((e0 - 2.0f * d0) * QSCALE, -32767.f), 32767.f));
                        int q1 = __float2int_rn(fminf(fmaxf((e1 - 2.0f * d1) * QSCALE, -32767.f), 32767.f));
                        int row0 = rowB + wr * 64 + mt * 16 + h * 8 + (lane >> 2);
                        *(short2*)&g_si[(size_t)row0 * KC + cb] =
                            make_short2((short)q0, (short)q1);
                        qmn[sl] = min(qmn[sl], min(q0, q1));
                        acc[mt][nt][h * 2] = 0.f;
                        acc[mt][nt][h * 2 + 1] = 0.f;
                    }
            }
#pragma unroll
            for (int off = 1; off <= 2; off <<= 1)
#pragma unroll
                for (int sl = 0; sl < 8; sl++)
                    qmn[sl] = min(qmn[sl], __shfl_xor_sync(0xffffffffu, qmn[sl], off));
            if ((lane & 3) == 0) {
#pragma unroll
                for (int sl = 0; sl < 8; sl++) {
                    int row0 = rowB + wr * 64 + (sl >> 1) * 16 + (sl & 1) * 8 + (lane >> 2);
                    atomicMin(&g_qmin[row0], qmn[sl]);
                }
            }
        }
        if (++cc == CHUNKS) { cc = 0; cu += NCTA; }
        ++it;
    }
}

// -------- refine: vectorized scan + exact argmin + gather + loss + finalize --------
__global__ __launch_bounds__(256)
void refine_kernel(const float* __restrict__ z, const float* __restrict__ emb,
                   float* __restrict__ ids_out, float* __restrict__ zq,
                   float* __restrict__ loss_out) {
    __shared__ float redl[8];
    const int w    = threadIdx.x >> 5;
    const int lane = threadIdx.x & 31;
    const int r    = blockIdx.x * 8 + w;

    const float zr = g_zsum[r];
    const int qthr = min(g_qmin[r] + QTHR_Q, 32767);
    const unsigned thr2 = ((unsigned)(unsigned short)qthr << 16) | (unsigned short)qthr;

    // z row in registers (exact fp32)
    float zreg[24];
    const float* zrow = z + (size_t)r * DIM;
#pragma unroll
    for (int j = 0; j < 24; j++) zreg[j] = zrow[lane + j * 32];

    // vectorized single-pass candidate scan: 16B per thread-iter, packed compares
    const int4* q4 = (const int4*)(g_si + (size_t)r * KC);
    int cand[4];
    int nc = 0;
#pragma unroll
    for (int j = 0; j < 8; j++) {
        int4 v = q4[lane + j * 32];
        unsigned m0 = __vcmples2((unsigned)v.x, thr2);
        unsigned m1 = __vcmples2((unsigned)v.y, thr2);
        unsigned m2 = __vcmples2((unsigned)v.z, thr2);
        unsigned m3 = __vcmples2((unsigned)v.w, thr2);
        if (m0 | m1 | m2 | m3) {
            const int base = (lane + j * 32) * 8;
            const unsigned mm[4] = {m0, m1, m2, m3};
#pragma unroll
            for (int t = 0; t < 4; t++) {
                if (mm[t] & 0xFFFFu) { if (nc < 4) cand[nc++] = base + t * 2; }
                if (mm[t] >> 16)     { if (nc < 4) cand[nc++] = base + t * 2 + 1; }
            }
        }
    }

    // warp-cooperative exact rescore (reference rounding, first-index ties)
    float best = 3.4e38f;
    int   bi   = INT_MAX;
    unsigned m = __ballot_sync(0xffffffffu, nc > 0);
    while (m) {
        int l = __ffs(m) - 1;
        m &= m - 1;
        int cnt = __shfl_sync(0xffffffffu, nc, l);
        for (int t = 0; t < cnt; t++) {
            int cc = __shfl_sync(0xffffffffu, cand[t], l);
            const float* erow = emb + (size_t)cc * DIM;
            float d = 0.f;
#pragma unroll
            for (int j = 0; j < 24; j++) d = fmaf(zreg[j], erow[lane + j * 32], d);
#pragma unroll
            for (int o = 16; o > 0; o >>= 1) d += __shfl_xor_sync(0xffffffffu, d, o);
            float se = (zr + g_enorm[cc]) - 2.0f * d;   // fl(fl(zsum+enorm)-2*dot)
            if (se < best || (se == best && cc < bi)) { best = se; bi = cc; }
        }
    }

    // gather z_q + commitment-loss partial
    const float* erow = emb + (size_t)bi * DIM;
    float* qrow = zq + (size_t)r * DIM;
    float lacc = 0.f;
#pragma unroll
    for (int j = 0; j < 24; j++) {
        float q = erow[lane + j * 32];
        qrow[lane + j * 32] = q;
        float dd = zreg[j] - q;
        lacc = fmaf(dd, dd, lacc);
    }
#pragma unroll
    for (int o = 16; o > 0; o >>= 1) lacc += __shfl_down_sync(0xffffffffu, lacc, o);
    if (lane == 0) {
        ids_out[r] = (float)bi;
        redl[w] = lacc;
    }
    __syncthreads();
    if (threadIdx.x == 0) {
        float t = 0.f;
#pragma unroll
        for (int i = 0; i < 8; i++) t += redl[i];
        atomicAdd(&g_loss, t);
        __threadfence();
        int old = atomicAdd(&g_cnt, 1);
        if (old == gridDim.x - 1) {
            float total = atomicAdd(&g_loss, 0.f);
            *loss_out = 0.25f * (total / (float)((long long)NROWS * DIM));
        }
    }
}

// ---------------- launch ----------------
extern "C" void kernel_launch(void* const* d_in, const int* in_sizes, int n_in,
                              void* d_out, int out_size) {
    (void)in_sizes; (void)n_in; (void)out_size;
    const float* z   = (const float*)d_in[0];
    const float* emb = (const float*)d_in[1];
    float* out   = (float*)d_out;
    float* zq    = out;                              // [NROWS*DIM]
    float* idsf  = out + (size_t)NROWS * DIM;        // [NROWS]
    float* lossp = idsf + NROWS;                     // [1]

    __nv_bfloat16 *zhi_p, *ehi_p;
    cudaGetSymbolAddress((void**)&zhi_p, g_zhi);
    cudaGetSymbolAddress((void**)&ehi_p, g_ehi);

    const int VQ_SMEM = 2 * STAGE + 128;            // 65664
    cudaFuncSetAttribute(vq_pass1_kernel, cudaFuncAttributeMaxDynamicSharedMemorySize, VQ_SMEM);

    prep_kernel<<<(NROWS + KC) / 8, 256>>>(z, emb, zhi_p, ehi_p);
    vq_pass1_kernel<<<NCTA, 128, VQ_SMEM>>>();
    refine_kernel<<<NROWS / 8, 256>>>(z, emb, idsf, zq, lossp);
}